// round 17
// baseline (speedup 1.0000x reference)
#include <cuda_runtime.h>
#include <cuda_bf16.h>
#include <cstdint>

#define B_    4
#define C_    64
#define T_    80
#define S_    2304
#define N_    128
#define NT_   10
#define TOUT_ 71
#define F_    320
#define KC    64
#define NCHUNK 36                 // chunks per tile
#define NTILE  160                // M128 tiles
#define GRID_G 152                // GB300 has 152 SMs
#define NLONG  136                // CTAs with 38 chunks; remaining 16 have 37

// ---------------- device scratch -------------------------------------------
__device__ float g_R2[2*B_*N_*T_];                       // [ord][b][n][t]
__device__ unsigned g_done = 0;                          // completion counter

// ---------------- helpers ---------------------------------------------------
__device__ __forceinline__ uint32_t smem_u32(const void* p) {
    uint32_t a;
    asm("{ .reg .u64 t; cvta.to.shared.u64 t, %1; cvt.u32.u64 %0, t; }" : "=r"(a) : "l"(p));
    return a;
}
__device__ __forceinline__ uint32_t pack_bf16(float lo, float hi) {
    uint32_t r;
    asm("cvt.rn.bf16x2.f32 %0, %1, %2;" : "=r"(r) : "f"(hi), "f"(lo));
    return r;
}
__device__ __forceinline__ void cp16(uint32_t dst, const void* src) {
    asm volatile("cp.async.cg.shared.global [%0], [%1], 16;" :: "r"(dst), "l"(src) : "memory");
}
#define CP_COMMIT() asm volatile("cp.async.commit_group;" ::: "memory")
#define CP_WAIT1()  asm volatile("cp.async.wait_group 1;" ::: "memory")

__device__ __forceinline__ void mma_bf16(float* d, const uint32_t* a, const uint32_t* b) {
    asm volatile("mma.sync.aligned.m16n8k16.row.col.f32.bf16.bf16.f32 "
        "{%0,%1,%2,%3}, {%4,%5,%6,%7}, {%8,%9}, {%0,%1,%2,%3};"
        : "+f"(d[0]), "+f"(d[1]), "+f"(d[2]), "+f"(d[3])
        : "r"(a[0]), "r"(a[1]), "r"(a[2]), "r"(a[3]), "r"(b[0]), "r"(b[1]));
}

// A: fp32 tile 128 rows x 256B, 32B granules g=0..7, XOR swizzle (proven)
__device__ __forceinline__ uint32_t aswz(int r, int g) {
    return (uint32_t)(r * 256 + (((g ^ (r & 7)) & 7) << 5));
}
// B: bf16 tile 128 rows x 128B, 16B granules (proven)
__device__ __forceinline__ uint32_t bswz(int n, int g) {
    return (uint32_t)(n * 128 + (((g ^ (n & 7)) & 7) << 4));
}

// ---------------------------------------------------------------------------
// GEMM + fused conv tail: grid 152, 512 threads, 3-stage cp.async A,
// rank-1 synthesized B; last CTA to finish runs the temporal conv.
// ---------------------------------------------------------------------------
#define SM_A    0          // 3 x 32768 (fp32)
#define SM_B    98304      // 2 x 16384 (bf16)
#define SM_GYZ  131072     // 36 x 128 fp32 = 18432
#define SM_T1   149504
#define T1_STRIDE 132
#define SMEM_SZ (149504 + 128*T1_STRIDE*4)   // 217088

extern "C" __global__ void __launch_bounds__(512, 1)
gemm_kernel(const float* __restrict__ x, const float* __restrict__ wc,
            const float* __restrict__ wx, const float* __restrict__ wy,
            const float* __restrict__ wsx, const float* __restrict__ wsy,
            const float* __restrict__ wt, const float* __restrict__ wb,
            float* __restrict__ out) {
    extern __shared__ __align__(16) char smem[];
    __shared__ unsigned s_last;
    const uint32_t sb = smem_u32(smem);
    const int tid  = threadIdx.x;
    const int wid  = tid >> 5;
    const int lane = tid & 31;
    const int wm   = wid & 3;       // m block: rows wm*32..+31
    const int wn   = wid >> 2;      // n block: cols wn*32..+31
    const int lrow = lane >> 2;
    const int lq   = lane & 3;
    const int lr   = tid >> 2;      // loader/synth row 0..127
    const int lz   = tid & 3;       // loader/synth quarter

    const int bi = blockIdx.x;
    const int s  = (bi < NLONG) ? 38 * bi : 38 * NLONG + 37 * (bi - NLONG);
    const int e  = s + ((bi < NLONG) ? 38 : 37);

    float* gyzs = (float*)(smem + SM_GYZ);   // [k][n]

    // ---- startup: gx in registers (x = lz*16+i, n = lr), gyz table ----
    float gxr[16];
    {
        float rx = fmaxf(wsx[lr], 0.0f);
        float i2x = 1.0f / (2.0f * (0.1f + rx * rx));
        float cx = wx[lr];
        float sgx = 0.0f;
#pragma unroll
        for (int i = 0; i < 16; i++) {
            float xv = ((float)(lz * 16 + i) - 32.0f + 0.5f) / 64.0f;
            float d = xv - cx;
            gxr[i] = expf(-d * d * i2x);
            sgx += gxr[i];
        }
        sgx += __shfl_xor_sync(0xFFFFFFFFu, sgx, 1);
        sgx += __shfl_xor_sync(0xFFFFFFFFu, sgx, 2);

        float ry = fmaxf(wsy[lr], 0.0f);
        float i2y = 1.0f / (2.0f * (0.1f + ry * ry));
        float cy = wy[lr];
        float gyv[9];
        float sgy = 0.0f;
#pragma unroll
        for (int i = 0; i < 9; i++) {
            float yv = ((float)(lz * 9 + i) - 18.0f + 0.5f) / 36.0f;
            float d = yv - cy;
            gyv[i] = expf(-d * d * i2y);
            sgy += gyv[i];
        }
        sgy += __shfl_xor_sync(0xFFFFFFFFu, sgy, 1);
        sgy += __shfl_xor_sync(0xFFFFFFFFu, sgy, 2);

        float iz = 1.0f / (0.1f + sgx * sgy);
#pragma unroll
        for (int i = 0; i < 9; i++)
            gyzs[(lz * 9 + i) * N_ + lr] = gyv[i] * iz;
    }
    __syncthreads();

    auto issueA = [&](int g, int p) {
        int m = g / NCHUNK;
        int k = g - m * NCHUNK;
        int gr = m * 128 + lr;
        int f  = gr >> 6;
        int c  = gr & 63;
        int bb = f / T_;
        int tt = f - bb * T_;
        const float* xrow = x + ((size_t)((bb * C_ + c) * T_ + tt)) * S_ + k * KC;
        uint32_t ab = sb + SM_A + (uint32_t)p * 32768u;
#pragma unroll
        for (int jj = 0; jj < 2; jj++) {
            int gA = lz * 2 + jj;                 // 32B granule
            uint32_t d = ab + aswz(lr, gA);
            cp16(d,      xrow + gA * 8);
            cp16(d + 16, xrow + gA * 8 + 4);
        }
    };

    // rank-1 B synthesis: B[n][j] = gyz[k][n] * gx[j][n]
    auto synthB = [&](int g, int stage) {
        int m = g / NCHUNK;
        int k = g - m * NCHUNK;
        float sc = gyzs[k * N_ + lr];
        uint32_t v[8];
#pragma unroll
        for (int q = 0; q < 8; q++)
            v[q] = pack_bf16(gxr[2 * q] * sc, gxr[2 * q + 1] * sc);
        uint32_t bb2 = sb + SM_B + (uint32_t)stage * 16384u;
        uint32_t d0 = bb2 + bswz(lr, lz * 2);
        uint32_t d1 = bb2 + bswz(lr, lz * 2 + 1);
        asm volatile("st.shared.v4.b32 [%0], {%1,%2,%3,%4};"
            :: "r"(d0), "r"(v[0]), "r"(v[1]), "r"(v[2]), "r"(v[3]) : "memory");
        asm volatile("st.shared.v4.b32 [%0], {%1,%2,%3,%4};"
            :: "r"(d1), "r"(v[4]), "r"(v[5]), "r"(v[6]), "r"(v[7]) : "memory");
    };

    float acc[2][4][4];
#pragma unroll
    for (int mt = 0; mt < 2; mt++)
#pragma unroll
        for (int j = 0; j < 4; j++)
#pragma unroll
            for (int q = 0; q < 4; q++) acc[mt][j][q] = 0.0f;

    issueA(s, 0);     CP_COMMIT();
    issueA(s + 1, 1); CP_COMMIT();

    float* Tsm = (float*)(smem + SM_T1);
    int pb = 0;                      // A stage of chunk g

    for (int g = s; g < e; g++) {
        synthB(g, g & 1);            // write B(g) before the barrier
        CP_WAIT1();                  // A(g) complete
        __syncthreads();

        const uint32_t Ab = sb + SM_A + (uint32_t)pb * 32768u;
        const uint32_t Bb = sb + SM_B + (uint32_t)(g & 1) * 16384u;
#pragma unroll
        for (int q = 0; q < 4; q++) {
            uint32_t afr[2][4];
#pragma unroll
            for (int mt = 0; mt < 2; mt++) {
#pragma unroll
                for (int half = 0; half < 2; half++) {
#pragma unroll
                    for (int dr = 0; dr < 2; dr++) {
                        float2 v;
                        uint32_t ad = Ab + aswz(wm * 32 + mt * 16 + lrow + dr * 8,
                                                q * 2 + half) + lq * 8;
                        asm volatile("ld.shared.v2.f32 {%0,%1}, [%2];"
                                     : "=f"(v.x), "=f"(v.y) : "r"(ad));
                        afr[mt][half * 2 + dr] = pack_bf16(v.x, v.y);
                    }
                }
            }
            uint32_t bfr[4][2];
#pragma unroll
            for (int j = 0; j < 4; j++) {
                int n = wn * 32 + j * 8 + lrow;
#pragma unroll
                for (int half = 0; half < 2; half++) {
                    asm volatile("ld.shared.b32 %0, [%1];"
                        : "=r"(bfr[j][half]) : "r"(Bb + bswz(n, q * 2 + half) + lq * 4));
                }
            }
#pragma unroll
            for (int mt = 0; mt < 2; mt++)
#pragma unroll
                for (int j = 0; j < 4; j++)
                    mma_bf16(acc[mt][j], afr[mt], bfr[j]);
        }

        if (g + 2 < e) {
            int pn = pb + 2; if (pn >= 3) pn -= 3;
            issueA(g + 2, pn);
        }
        CP_COMMIT();

        // ---- tile boundary or range end: flush partial R ----
        if ((g + 1 == e) || ((g + 1) % NCHUNK == 0)) {
            int m = g / NCHUNK;
            __syncthreads();
#pragma unroll
            for (int mt = 0; mt < 2; mt++) {
#pragma unroll
                for (int j = 0; j < 4; j++) {
                    int r0  = wm * 32 + mt * 16 + lrow;
                    int col = wn * 32 + j * 8 + lq * 2;
                    uint32_t a0 = sb + SM_T1 + (uint32_t)((r0 * T1_STRIDE + col) * 4);
                    uint32_t a1 = sb + SM_T1 + (uint32_t)(((r0 + 8) * T1_STRIDE + col) * 4);
                    asm volatile("st.shared.v2.f32 [%0], {%1,%2};"
                                 :: "r"(a0), "f"(acc[mt][j][0]), "f"(acc[mt][j][1]));
                    asm volatile("st.shared.v2.f32 [%0], {%1,%2};"
                                 :: "r"(a1), "f"(acc[mt][j][2]), "f"(acc[mt][j][3]));
                }
            }
            __syncthreads();
            if (tid < 256) {
                int fl = tid >> 7;
                int n  = tid & 127;
                float sum = 0.0f;
#pragma unroll 16
                for (int c2 = 0; c2 < 64; c2++)
                    sum += Tsm[(fl * 64 + c2) * T1_STRIDE + n] * __ldg(&wc[c2 * N_ + n]);
                int ord = (s > m * NCHUNK) ? 1 : 0;
                int f2 = m * 2 + fl;
                int b2 = f2 / T_;
                int t2 = f2 - b2 * T_;
                g_R2[(size_t)(ord * 512 + b2 * 128 + n) * T_ + t2] = sum;
                // sole writer of this tile -> ord-1 slot never written: zero it
                if (ord == 0 && e >= (m + 1) * NCHUNK)
                    g_R2[(size_t)(512 + b2 * 128 + n) * T_ + t2] = 0.0f;
            }
#pragma unroll
            for (int mt = 0; mt < 2; mt++)
#pragma unroll
                for (int j = 0; j < 4; j++)
#pragma unroll
                    for (int q = 0; q < 4; q++) acc[mt][j][q] = 0.0f;
        }

        if (++pb >= 3) pb = 0;
    }

    // ---- fused conv tail: last CTA to finish does the temporal conv ----
    __threadfence();
    if (tid == 0) {
        unsigned old = atomicAdd(&g_done, 1u);
        s_last = (old == GRID_G - 1) ? 1u : 0u;
    }
    __syncthreads();
    if (s_last) {
        const int row = tid;                     // row = b*N + n, 0..511
        const int n = row & 127;
        float rr[80];
        const float4* r0 = (const float4*)(g_R2 + (size_t)row * T_);
        const float4* r1 = (const float4*)(g_R2 + (size_t)(512 + row) * T_);
#pragma unroll
        for (int i = 0; i < 20; i++) {
            float4 a = __ldg(r0 + i);
            float4 b = __ldg(r1 + i);
            rr[4 * i]     = a.x + b.x;
            rr[4 * i + 1] = a.y + b.y;
            rr[4 * i + 2] = a.z + b.z;
            rr[4 * i + 3] = a.w + b.w;
        }
        float wts[NT_];
#pragma unroll
        for (int k = 0; k < NT_; k++) wts[k] = __ldg(&wt[k * N_ + n]);
        float bias = __ldg(&wb[n]);
        float* op = out + (size_t)row * TOUT_;
#pragma unroll
        for (int t0 = 0; t0 < TOUT_; t0++) {
            float sum = bias;
#pragma unroll
            for (int k = 0; k < NT_; k++) sum += rr[t0 + k] * wts[k];
            op[t0] = sum;
        }
        if (tid == 0) g_done = 0;                // reset for graph replay
    }
}

// ---------------------------------------------------------------------------
extern "C" void kernel_launch(void* const* d_in, const int* in_sizes, int n_in,
                              void* d_out, int out_size) {
    (void)in_sizes; (void)n_in; (void)out_size;
    const float* x   = (const float*)d_in[0];
    const float* wc  = (const float*)d_in[2];
    const float* wx  = (const float*)d_in[3];
    const float* wy  = (const float*)d_in[4];
    const float* wsx = (const float*)d_in[5];
    const float* wsy = (const float*)d_in[6];
    const float* wt  = (const float*)d_in[7];
    const float* wb  = (const float*)d_in[8];
    float* out = (float*)d_out;

    cudaFuncSetAttribute(gemm_kernel, cudaFuncAttributeMaxDynamicSharedMemorySize, SMEM_SZ);

    gemm_kernel<<<GRID_G, 512, SMEM_SZ>>>(x, wc, wx, wy, wsx, wsy, wt, wb, out);
}